// round 13
// baseline (speedup 1.0000x reference)
#include <cuda_runtime.h>
#include <cuda_fp16.h>
#include <math.h>
#include <stdint.h>

#define Bn 8
#define Sn 2048
#define En 512
#define BSn (Bn * Sn)  // 16384

__device__ __constant__ float c_inv_scale = 0.044194173824159216f; // 1/sqrt(512)

// ---------------- scratch ---------------------------------------------------
__device__ __half g_hhi[(size_t)BSn * En];
__device__ __half g_wThi[(size_t)En * En];       // [e_out][e_in]
__device__ __half g_qhi[(size_t)BSn * En];       // pre-scaled by 1/sqrt(E)
__device__ __half g_khi[(size_t)BSn * En];
__device__ __half g_vThi[(size_t)Bn * En * Sn];  // [b][e][t]
__device__ __half g_dhi[(size_t)Bn * Sn * Sn];   // delta fp16 [b*S+s][t]
__device__ float g_rowsum[BSn];

// ---------------- helpers ----------------------------------------------------
__device__ __forceinline__ uint32_t smem_u32(const void* p) {
    uint32_t a;
    asm("{ .reg .u64 t; cvta.to.shared.u64 t, %1; cvt.u32.u64 %0, t; }"
        : "=r"(a) : "l"(p));
    return a;
}
__device__ __forceinline__ void ldsm_x4(uint32_t (&r)[4], uint32_t addr) {
    asm volatile(
        "ldmatrix.sync.aligned.m8n8.x4.shared.b16 {%0,%1,%2,%3}, [%4];"
        : "=r"(r[0]), "=r"(r[1]), "=r"(r[2]), "=r"(r[3]) : "r"(addr));
}
__device__ __forceinline__ void mma16816(float (&d)[4], const uint32_t (&a)[4],
                                         uint32_t b0, uint32_t b1) {
    asm volatile(
        "mma.sync.aligned.m16n8k16.row.col.f32.f16.f16.f32 "
        "{%0,%1,%2,%3}, {%4,%5,%6,%7}, {%8,%9}, {%0,%1,%2,%3};"
        : "+f"(d[0]), "+f"(d[1]), "+f"(d[2]), "+f"(d[3])
        : "r"(a[0]), "r"(a[1]), "r"(a[2]), "r"(a[3]), "r"(b0), "r"(b1));
}
// .ca restored — L1 staging of reused operand tiles measurably helps (R12)
#define CPA16(dst, src) \
    asm volatile("cp.async.ca.shared.global [%0], [%1], 16;" \
                 :: "r"(dst), "l"(src) : "memory")
#define CPA_COMMIT() asm volatile("cp.async.commit_group;" ::: "memory")
#define CPA_WAIT2() asm volatile("cp.async.wait_group 2;" ::: "memory")
#define CPA_WAIT1() asm volatile("cp.async.wait_group 1;" ::: "memory")
#define CPA_WAIT0() asm volatile("cp.async.wait_group 0;" ::: "memory")

__device__ __forceinline__ uint32_t h2u(__half a, __half b) {
    __half2 p = __halves2half2(a, b);
    return *reinterpret_cast<uint32_t*>(&p);
}

// ---------------------------------------------------------------------------
// 4-stage cp.async pipelined fp16 HMMA mainloop, block tile 64x256:
//   acc += A·B^T over K = ktot.  A (64 rows), B (256 rows), K-major fp16.
// 256 threads, 8 warps in 2(M)x4(N) grid, warp tile 32x64, K-chunk 32.
// smem/stage: A 64x40h (5120 B) + B 256x40h (20480 B) = 25600 B.
// 2 CTAs/SM -> 4 warps/SMSP for latency hiding.
// ---------------------------------------------------------------------------
#define PAD 40
#define TILEA 5120
#define TILEBB 20480
#define ST (TILEA + TILEBB)   // 25600
#define STAGES 4
#define SMEM_GB (STAGES * ST) // 102400

__device__ __forceinline__ void hmma_pipe(
    const __half* __restrict__ A, const __half* __restrict__ B, int lda,
    int ldb, int ktot, float (&acc)[2][8][4]) {
    extern __shared__ __align__(16) __half sm[];
    const uint32_t s0 = smem_u32(sm);

    const int tid = threadIdx.x;
    const int w = tid >> 5, l = tid & 31;
    const int wm = (w & 1) * 32, wn = (w >> 1) * 64;
    const int lrow = l & 7, quad = l >> 3;

    // loaders: A: 4 thr/row x 16B; B: 1 thr/row x 64B
    const int arow = tid >> 2;
    const int acol = (tid & 3) * 8;  // halves
    const uint32_t adst = (uint32_t)(arow * PAD + acol) * 2;
    const uint32_t bdst = TILEA + (uint32_t)tid * PAD * 2;

    const int nck = ktot / 32;

    uint32_t a_addr[2][2], b_addr[4][2];
#pragma unroll
    for (int mi = 0; mi < 2; mi++)
#pragma unroll
        for (int ks = 0; ks < 2; ks++)
            a_addr[mi][ks] = s0 + ((wm + mi * 16 + (quad & 1) * 8 + lrow) * PAD +
                                   ks * 16 + (quad >> 1) * 8) * 2;
#pragma unroll
    for (int bi = 0; bi < 4; bi++)
#pragma unroll
        for (int ks = 0; ks < 2; ks++)
            b_addr[bi][ks] = s0 + TILEA +
                             ((wn + bi * 16 + (quad >> 1) * 8 + lrow) * PAD +
                              ks * 16 + (quad & 1) * 8) * 2;

    auto load_chunk = [&](int c) {
        const uint32_t base = s0 + (uint32_t)(c & (STAGES - 1)) * ST;
        const __half* pa = A + (size_t)arow * lda + c * 32 + acol;
        CPA16(base + adst, pa);
        const __half* pb = B + (size_t)tid * ldb + c * 32;
        CPA16(base + bdst, pb);
        CPA16(base + bdst + 16, pb + 8);
        CPA16(base + bdst + 32, pb + 16);
        CPA16(base + bdst + 48, pb + 24);
    };

    load_chunk(0);
    CPA_COMMIT();
    load_chunk(1);
    CPA_COMMIT();
    load_chunk(2);
    CPA_COMMIT();

    for (int c = 0; c < nck; c++) {
        if (c <= nck - 3) {
            CPA_WAIT2();
        } else if (c == nck - 2) {
            CPA_WAIT1();
        } else {
            CPA_WAIT0();
        }
        __syncthreads();
        if (c + 3 < nck) {
            load_chunk(c + 3);
            CPA_COMMIT();
        }
        const uint32_t boff = (uint32_t)(c & (STAGES - 1)) * ST;
#pragma unroll
        for (int ks = 0; ks < 2; ks++) {
            uint32_t ah[2][4], bh[4][4];
#pragma unroll
            for (int mi = 0; mi < 2; mi++) ldsm_x4(ah[mi], a_addr[mi][ks] + boff);
#pragma unroll
            for (int bi = 0; bi < 4; bi++) ldsm_x4(bh[bi], b_addr[bi][ks] + boff);
#pragma unroll
            for (int mi = 0; mi < 2; mi++)
#pragma unroll
                for (int ni = 0; ni < 8; ni++)
                    mma16816(acc[mi][ni], ah[mi], bh[ni >> 1][(ni & 1) * 2],
                             bh[ni >> 1][(ni & 1) * 2 + 1]);
        }
    }
}

// ---------------------------------------------------------------------------
// Mega prep kernel (merged): hidden-convert, W-transpose, K-gather(+rowsum 0),
// V-gather/transpose, dispatched by block range, one wave.
// ---------------------------------------------------------------------------
#define HID_BLOCKS ((int)((size_t)BSn * En / 8 / 256))   // 4096
#define W_BLOCKS (En * En / 256)                         // 1024
#define K_BLOCKS (BSn / 2)                               // 8192
#define VT_BLOCKS (Bn * (En / 64) * (Sn / 64))           // 2048
#define PREP_BLOCKS (HID_BLOCKS + W_BLOCKS + K_BLOCKS + VT_BLOCKS)

__global__ __launch_bounds__(256) void prep_all(
    const float* __restrict__ h, const float* __restrict__ W,
    const int* __restrict__ kseq, const float* __restrict__ kemb,
    const int* __restrict__ vseq, const float* __restrict__ vemb) {
    const int bid = blockIdx.x;
    const int tid = threadIdx.x;
    if (bid < HID_BLOCKS) {
        const size_t i8 = ((size_t)bid * 256 + tid) * 8;
        const float4 f0 = *(const float4*)(h + i8);
        const float4 f1 = *(const float4*)(h + i8 + 4);
        *(uint4*)(g_hhi + i8) = make_uint4(
            h2u(__float2half_rn(f0.x), __float2half_rn(f0.y)),
            h2u(__float2half_rn(f0.z), __float2half_rn(f0.w)),
            h2u(__float2half_rn(f1.x), __float2half_rn(f1.y)),
            h2u(__float2half_rn(f1.z), __float2half_rn(f1.w)));
        return;
    }
    if (bid < HID_BLOCKS + W_BLOCKS) {
        const int idx = (bid - HID_BLOCKS) * 256 + tid;
        const int eo = idx >> 9;
        const int ei = idx & 511;
        g_wThi[idx] = __float2half_rn(W[(size_t)ei * En + eo]);
        return;
    }
    if (bid < HID_BLOCKS + W_BLOCKS + K_BLOCKS) {
        const int base = (bid - HID_BLOCKS - W_BLOCKS) * 2;
        const int row = base + (tid >> 7);
        const int t = tid & 127;
        if (t == 0) g_rowsum[row] = 0.0f;
        const int ki = kseq[row];
        const float4 f = *(const float4*)(kemb + (size_t)ki * En + t * 4);
        *(uint2*)(g_khi + (size_t)row * En + t * 4) =
            make_uint2(h2u(__float2half_rn(f.x), __float2half_rn(f.y)),
                       h2u(__float2half_rn(f.z), __float2half_rn(f.w)));
        return;
    }
    {
        __shared__ float tile[64][65];
        const int vb = bid - HID_BLOCKS - W_BLOCKS - K_BLOCKS;
        const int tblk = vb & 31;
        const int eblk = (vb >> 5) & 7;
        const int b = vb >> 8;
        const int e0 = eblk * 64;
        const int t0 = tblk * 64;
        const int tr = tid >> 4;
        const int tc = (tid & 15) * 4;
#pragma unroll
        for (int rr = 0; rr < 4; rr++) {
            const int tl = tr + rr * 16;
            const int vi = vseq[b * Sn + t0 + tl];
            const float4 f = *(const float4*)(vemb + (size_t)vi * En + e0 + tc);
            tile[tl][tc + 0] = f.x;
            tile[tl][tc + 1] = f.y;
            tile[tl][tc + 2] = f.z;
            tile[tl][tc + 3] = f.w;
        }
        __syncthreads();
        const int er = tid >> 3;
        const int seg = (tid & 7) * 8;
#pragma unroll
        for (int pp = 0; pp < 2; pp++) {
            const int el = er + pp * 32;
            __half hh[8];
#pragma unroll
            for (int j = 0; j < 8; j++) hh[j] = __float2half_rn(tile[seg + j][el]);
            const size_t o = ((size_t)b * En + e0 + el) * Sn + t0 + seg;
            *(uint4*)(g_vThi + o) =
                make_uint4(h2u(hh[0], hh[1]), h2u(hh[2], hh[3]),
                           h2u(hh[4], hh[5]), h2u(hh[6], hh[7]));
        }
    }
}

// ---------------------------------------------------------------------------
// GEMM kernels (256 threads, 2 CTAs/SM, dynamic smem SMEM_GB)
// ---------------------------------------------------------------------------
__global__ __launch_bounds__(256, 2) void qgemm_h() {
    const int s0 = blockIdx.y * 64;
    const int n0 = blockIdx.x * 256;
    float acc[2][8][4] = {};
    hmma_pipe(g_hhi + (size_t)s0 * En, g_wThi + (size_t)n0 * En, En, En, En,
              acc);
    const int tid = threadIdx.x;
    const int w = tid >> 5, l = tid & 31;
    const int wm = (w & 1) * 32, wn = (w >> 1) * 64;
#pragma unroll
    for (int mi = 0; mi < 2; mi++) {
#pragma unroll
        for (int rh = 0; rh < 2; rh++) {
            const int row = s0 + wm + mi * 16 + (l >> 2) + rh * 8;
#pragma unroll
            for (int ni = 0; ni < 8; ni++) {
                const int col = n0 + wn + ni * 8 + (l & 3) * 2;
                const size_t o = (size_t)row * En + col;
                *(uint32_t*)(g_qhi + o) =
                    h2u(__float2half_rn(acc[mi][ni][rh * 2] * c_inv_scale),
                        __float2half_rn(acc[mi][ni][rh * 2 + 1] * c_inv_scale));
            }
        }
    }
}

// grid = (t-blocks = Sn/256 = 8, s-blocks = Sn/64 = 32, b = 8)
__global__ __launch_bounds__(256, 2) void scores_h(const float* __restrict__ mask) {
    const int b = blockIdx.z;
    const int s0 = blockIdx.y * 64;
    const int t0 = blockIdx.x * 256;
    const int tid = threadIdx.x;
    const size_t qoff = ((size_t)b * Sn + s0) * En;
    const size_t koff = ((size_t)b * Sn + t0) * En;
    float acc[2][8][4] = {};
    hmma_pipe(g_qhi + qoff, g_khi + koff, En, En, En, acc);

    __shared__ float rsum[64];
    if (tid < 64) rsum[tid] = 0.0f;
    __syncthreads();
    const int w = tid >> 5, l = tid & 31;
    const int wm = (w & 1) * 32, wn = (w >> 1) * 64;
#pragma unroll
    for (int mi = 0; mi < 2; mi++) {
#pragma unroll
        for (int rh = 0; rh < 2; rh++) {
            const int lr = wm + mi * 16 + (l >> 2) + rh * 8;
            const size_t grow = (size_t)b * Sn + s0 + lr;
            const float* mrow = mask + grow * Sn + t0;
            __half* dh = g_dhi + grow * Sn + t0;
            float part = 0.0f;
#pragma unroll
            for (int ni = 0; ni < 8; ni++) {
                const int col = wn + ni * 8 + (l & 3) * 2;
                const float2 m2 = *(const float2*)(mrow + col);
                const float mc0 = fminf(fmaxf(m2.x, 0.0f), 1.0f);
                const float mc1 = fminf(fmaxf(m2.y, 0.0f), 1.0f);
                const __half h0 = __float2half_rn(__expf(acc[mi][ni][rh * 2]) * mc0);
                const __half h1 = __float2half_rn(__expf(acc[mi][ni][rh * 2 + 1]) * mc1);
                part += __half2float(h0) + __half2float(h1);
                *(uint32_t*)(dh + col) = h2u(h0, h1);
            }
            part += __shfl_xor_sync(0xFFFFFFFF, part, 1);
            part += __shfl_xor_sync(0xFFFFFFFF, part, 2);
            if ((l & 3) == 0) atomicAdd(&rsum[lr], part);
        }
    }
    __syncthreads();
    if (tid < 64) atomicAdd(&g_rowsum[(size_t)b * Sn + s0 + tid], rsum[tid]);
}

// grid = (e-blocks = En/256 = 2, s-blocks = 32, b = 8)
__global__ __launch_bounds__(256, 2) void outgemm_h(float* __restrict__ out) {
    const int b = blockIdx.z;
    const int s0 = blockIdx.y * 64;
    const int e0 = blockIdx.x * 256;
    const size_t doff = ((size_t)b * Sn + s0) * Sn;
    const size_t voff = ((size_t)b * En + e0) * Sn;
    float acc[2][8][4] = {};
    hmma_pipe(g_dhi + doff, g_vThi + voff, Sn, Sn, Sn, acc);
    const int tid = threadIdx.x;
    const int w = tid >> 5, l = tid & 31;
    const int wm = (w & 1) * 32, wn = (w >> 1) * 64;
#pragma unroll
    for (int mi = 0; mi < 2; mi++) {
#pragma unroll
        for (int rh = 0; rh < 2; rh++) {
            const int lr = wm + mi * 16 + (l >> 2) + rh * 8;
            const size_t grow = (size_t)b * Sn + s0 + lr;
            const float inv = 1.0f / (g_rowsum[grow] + 1e-10f);
            float* orow = out + grow * En + e0;
#pragma unroll
            for (int ni = 0; ni < 8; ni++) {
                const int col = wn + ni * 8 + (l & 3) * 2;
                *(float2*)(orow + col) =
                    make_float2(acc[mi][ni][rh * 2] * inv,
                                acc[mi][ni][rh * 2 + 1] * inv);
            }
        }
    }
}

// ---------------------------------------------------------------------------
extern "C" void kernel_launch(void* const* d_in, const int* in_sizes, int n_in,
                              void* d_out, int out_size) {
    const int* key_seq = (const int*)d_in[0];
    const int* value_seq = (const int*)d_in[1];
    const float* hidden = (const float*)d_in[2];
    const float* mask = (const float*)d_in[3];
    const float* key_emb = (const float*)d_in[5];
    const float* value_emb = (const float*)d_in[6];
    const float* weight = (const float*)d_in[7];
    float* out = (float*)d_out;

    cudaFuncSetAttribute(qgemm_h, cudaFuncAttributeMaxDynamicSharedMemorySize,
                         SMEM_GB);
    cudaFuncSetAttribute(scores_h, cudaFuncAttributeMaxDynamicSharedMemorySize,
                         SMEM_GB);
    cudaFuncSetAttribute(outgemm_h, cudaFuncAttributeMaxDynamicSharedMemorySize,
                         SMEM_GB);

    prep_all<<<PREP_BLOCKS, 256>>>(hidden, weight, key_seq, key_emb, value_seq,
                                   value_emb);
    qgemm_h<<<dim3(En / 256, BSn / 64), 256, SMEM_GB>>>();
    scores_h<<<dim3(Sn / 256, Sn / 64, Bn), 256, SMEM_GB>>>(mask);
    outgemm_h<<<dim3(En / 256, Sn / 64, Bn), 256, SMEM_GB>>>(out);
}

// round 14
// speedup vs baseline: 1.6716x; 1.6716x over previous
#include <cuda_runtime.h>
#include <cuda_fp16.h>
#include <math.h>
#include <stdint.h>

#define Bn 8
#define Sn 2048
#define En 512
#define BSn (Bn * Sn)  // 16384

__device__ __constant__ float c_inv_scale = 0.044194173824159216f; // 1/sqrt(512)

// ---------------- scratch ---------------------------------------------------
__device__ __half g_hhi[(size_t)BSn * En];
__device__ __half g_wThi[(size_t)En * En];       // [e_out][e_in]
__device__ __half g_qhi[(size_t)BSn * En];       // pre-scaled by 1/sqrt(E)
__device__ __half g_khi[(size_t)BSn * En];
__device__ __half g_vThi[(size_t)Bn * En * Sn];  // [b][e][t]
__device__ __half g_dhi[(size_t)Bn * Sn * Sn];   // delta fp16 [b*S+s][t]
__device__ float g_rowsum[BSn];

// ---------------- helpers ----------------------------------------------------
__device__ __forceinline__ uint32_t smem_u32(const void* p) {
    uint32_t a;
    asm("{ .reg .u64 t; cvta.to.shared.u64 t, %1; cvt.u32.u64 %0, t; }"
        : "=r"(a) : "l"(p));
    return a;
}
__device__ __forceinline__ void ldsm_x4(uint32_t (&r)[4], uint32_t addr) {
    asm volatile(
        "ldmatrix.sync.aligned.m8n8.x4.shared.b16 {%0,%1,%2,%3}, [%4];"
        : "=r"(r[0]), "=r"(r[1]), "=r"(r[2]), "=r"(r[3]) : "r"(addr));
}
__device__ __forceinline__ void mma16816(float (&d)[4], const uint32_t (&a)[4],
                                         uint32_t b0, uint32_t b1) {
    asm volatile(
        "mma.sync.aligned.m16n8k16.row.col.f32.f16.f16.f32 "
        "{%0,%1,%2,%3}, {%4,%5,%6,%7}, {%8,%9}, {%0,%1,%2,%3};"
        : "+f"(d[0]), "+f"(d[1]), "+f"(d[2]), "+f"(d[3])
        : "r"(a[0]), "r"(a[1]), "r"(a[2]), "r"(a[3]), "r"(b0), "r"(b1));
}
#define CPA16(dst, src) \
    asm volatile("cp.async.ca.shared.global [%0], [%1], 16;" \
                 :: "r"(dst), "l"(src) : "memory")
#define CPA_COMMIT() asm volatile("cp.async.commit_group;" ::: "memory")
#define CPA_WAIT2() asm volatile("cp.async.wait_group 2;" ::: "memory")
#define CPA_WAIT1() asm volatile("cp.async.wait_group 1;" ::: "memory")
#define CPA_WAIT0() asm volatile("cp.async.wait_group 0;" ::: "memory")

__device__ __forceinline__ uint32_t h2u(__half a, __half b) {
    __half2 p = __halves2half2(a, b);
    return *reinterpret_cast<uint32_t*>(&p);
}

// ---------------------------------------------------------------------------
// 4-stage cp.async pipelined fp16 HMMA mainloop, block tile 128x256 (R11),
// with REGISTER FRAGMENT DOUBLE-BUFFERING: all 16 ldsm for both ks-groups
// are issued before the MMAs, so ks=1 loads complete under ks=0 MMAs.
// 256 threads, 8 warps in 2(M)x4(N) grid, warp tile 64x64, K-chunk 32.
// ---------------------------------------------------------------------------
#define PAD 40
#define TILEA 10240
#define TILEBB 20480
#define ST (TILEA + TILEBB)   // 30720
#define STAGES 4
#define SMEM_GB (STAGES * ST) // 122880

__device__ __forceinline__ void hmma_pipe(
    const __half* __restrict__ A, const __half* __restrict__ B, int lda,
    int ldb, int ktot, float (&acc)[4][8][4]) {
    extern __shared__ __align__(16) __half sm[];
    const uint32_t s0 = smem_u32(sm);

    const int tid = threadIdx.x;
    const int w = tid >> 5, l = tid & 31;
    const int wm = (w & 1) * 64, wn = (w >> 1) * 64;
    const int lrow = l & 7, quad = l >> 3;

    const int arow = tid >> 1;
    const int acol = (tid & 1) * 16;  // halves
    const uint32_t adst = (uint32_t)(arow * PAD + acol) * 2;
    const uint32_t bdst = TILEA + (uint32_t)tid * PAD * 2;

    const int nck = ktot / 32;

    // ks=0 base addresses; ks=1 = +32 bytes (16 halves)
    uint32_t a_addr[4], b_addr[4];
#pragma unroll
    for (int mi = 0; mi < 4; mi++)
        a_addr[mi] = s0 + ((wm + mi * 16 + (quad & 1) * 8 + lrow) * PAD +
                           (quad >> 1) * 8) * 2;
#pragma unroll
    for (int bi = 0; bi < 4; bi++)
        b_addr[bi] = s0 + TILEA +
                     ((wn + bi * 16 + (quad >> 1) * 8 + lrow) * PAD +
                      (quad & 1) * 8) * 2;

    auto load_chunk = [&](int c) {
        const uint32_t base = s0 + (uint32_t)(c & (STAGES - 1)) * ST;
        const __half* pa = A + (size_t)arow * lda + c * 32 + acol;
        CPA16(base + adst, pa);
        CPA16(base + adst + 16, pa + 8);
        const __half* pb = B + (size_t)tid * ldb + c * 32;
        CPA16(base + bdst, pb);
        CPA16(base + bdst + 16, pb + 8);
        CPA16(base + bdst + 32, pb + 16);
        CPA16(base + bdst + 48, pb + 24);
    };

    load_chunk(0);
    CPA_COMMIT();
    load_chunk(1);
    CPA_COMMIT();
    load_chunk(2);
    CPA_COMMIT();

    for (int c = 0; c < nck; c++) {
        if (c <= nck - 3) {
            CPA_WAIT2();
        } else if (c == nck - 2) {
            CPA_WAIT1();
        } else {
            CPA_WAIT0();
        }
        __syncthreads();
        if (c + 3 < nck) {
            load_chunk(c + 3);
            CPA_COMMIT();
        }
        const uint32_t boff = (uint32_t)(c & (STAGES - 1)) * ST;

        // Issue ALL fragment loads first (both ks buffers); scoreboard lets
        // ks=0 MMAs begin once ks=0 frags land, ks=1 loads finish in shadow.
        uint32_t ah[2][4][4], bh[2][4][4];
#pragma unroll
        for (int mi = 0; mi < 4; mi++) ldsm_x4(ah[0][mi], a_addr[mi] + boff);
#pragma unroll
        for (int bi = 0; bi < 4; bi++) ldsm_x4(bh[0][bi], b_addr[bi] + boff);
#pragma unroll
        for (int mi = 0; mi < 4; mi++)
            ldsm_x4(ah[1][mi], a_addr[mi] + boff + 32);
#pragma unroll
        for (int bi = 0; bi < 4; bi++)
            ldsm_x4(bh[1][bi], b_addr[bi] + boff + 32);

#pragma unroll
        for (int ks = 0; ks < 2; ks++)
#pragma unroll
            for (int mi = 0; mi < 4; mi++)
#pragma unroll
                for (int ni = 0; ni < 8; ni++)
                    mma16816(acc[mi][ni], ah[ks][mi],
                             bh[ks][ni >> 1][(ni & 1) * 2],
                             bh[ks][ni >> 1][(ni & 1) * 2 + 1]);
    }
}

// ---------------------------------------------------------------------------
// Prep kernels (R11 layout: three separate launches)
// ---------------------------------------------------------------------------
#define HID_BLOCKS ((int)((size_t)BSn * En / 8 / 256))  // 4096
#define W_BLOCKS (En * En / 256)                        // 1024

__global__ __launch_bounds__(256) void prep_hw(const float* __restrict__ h,
                                               const float* __restrict__ W) {
    const int bid = blockIdx.x;
    if (bid < HID_BLOCKS) {
        const size_t i8 = ((size_t)bid * 256 + threadIdx.x) * 8;
        const float4 f0 = *(const float4*)(h + i8);
        const float4 f1 = *(const float4*)(h + i8 + 4);
        *(uint4*)(g_hhi + i8) = make_uint4(
            h2u(__float2half_rn(f0.x), __float2half_rn(f0.y)),
            h2u(__float2half_rn(f0.z), __float2half_rn(f0.w)),
            h2u(__float2half_rn(f1.x), __float2half_rn(f1.y)),
            h2u(__float2half_rn(f1.z), __float2half_rn(f1.w)));
    } else {
        const int idx = (bid - HID_BLOCKS) * 256 + threadIdx.x;
        const int eo = idx >> 9;
        const int ei = idx & 511;
        g_wThi[idx] = __float2half_rn(W[(size_t)ei * En + eo]);
    }
}

__global__ __launch_bounds__(128) void gather_k(const int* __restrict__ kseq,
                                                const float* __restrict__ kemb) {
    const int row = blockIdx.x;
    const int t = threadIdx.x;
    if (t == 0) g_rowsum[row] = 0.0f;
    const int ki = kseq[row];
    const float4 f = *(const float4*)(kemb + (size_t)ki * En + t * 4);
    *(uint2*)(g_khi + (size_t)row * En + t * 4) =
        make_uint2(h2u(__float2half_rn(f.x), __float2half_rn(f.y)),
                   h2u(__float2half_rn(f.z), __float2half_rn(f.w)));
}

__global__ __launch_bounds__(256) void gather_vT(const int* __restrict__ vseq,
                                                 const float* __restrict__ vemb) {
    __shared__ float tile[64][65];
    const int b = blockIdx.z;
    const int e0 = blockIdx.y * 64;
    const int t0 = blockIdx.x * 64;
    const int tid = threadIdx.x;
    const int tr = tid >> 4;
    const int tc = (tid & 15) * 4;
#pragma unroll
    for (int rr = 0; rr < 4; rr++) {
        const int tl = tr + rr * 16;
        const int vi = vseq[b * Sn + t0 + tl];
        const float4 f = *(const float4*)(vemb + (size_t)vi * En + e0 + tc);
        tile[tl][tc + 0] = f.x;
        tile[tl][tc + 1] = f.y;
        tile[tl][tc + 2] = f.z;
        tile[tl][tc + 3] = f.w;
    }
    __syncthreads();
    const int er = tid >> 3;
    const int seg = (tid & 7) * 8;
#pragma unroll
    for (int pp = 0; pp < 2; pp++) {
        const int el = er + pp * 32;
        __half hh[8];
#pragma unroll
        for (int j = 0; j < 8; j++) hh[j] = __float2half_rn(tile[seg + j][el]);
        const size_t o = ((size_t)b * En + e0 + el) * Sn + t0 + seg;
        *(uint4*)(g_vThi + o) = make_uint4(h2u(hh[0], hh[1]), h2u(hh[2], hh[3]),
                                           h2u(hh[4], hh[5]), h2u(hh[6], hh[7]));
    }
}

// ---------------------------------------------------------------------------
// GEMM kernels (256 threads, 1 CTA/SM, dynamic smem SMEM_GB)
// ---------------------------------------------------------------------------
__global__ __launch_bounds__(256, 1) void qgemm_h() {
    const int s0 = blockIdx.y * 128;
    const int n0 = blockIdx.x * 256;
    float acc[4][8][4] = {};
    hmma_pipe(g_hhi + (size_t)s0 * En, g_wThi + (size_t)n0 * En, En, En, En,
              acc);
    const int tid = threadIdx.x;
    const int w = tid >> 5, l = tid & 31;
    const int wm = (w & 1) * 64, wn = (w >> 1) * 64;
#pragma unroll
    for (int mi = 0; mi < 4; mi++) {
#pragma unroll
        for (int rh = 0; rh < 2; rh++) {
            const int row = s0 + wm + mi * 16 + (l >> 2) + rh * 8;
#pragma unroll
            for (int ni = 0; ni < 8; ni++) {
                const int col = n0 + wn + ni * 8 + (l & 3) * 2;
                const size_t o = (size_t)row * En + col;
                *(uint32_t*)(g_qhi + o) =
                    h2u(__float2half_rn(acc[mi][ni][rh * 2] * c_inv_scale),
                        __float2half_rn(acc[mi][ni][rh * 2 + 1] * c_inv_scale));
            }
        }
    }
}

// grid = (t-blocks = Sn/256 = 8, s-blocks = 16, b = 8)
__global__ __launch_bounds__(256, 1) void scores_h(const float* __restrict__ mask) {
    const int b = blockIdx.z;
    const int s0 = blockIdx.y * 128;
    const int t0 = blockIdx.x * 256;
    const int tid = threadIdx.x;
    const size_t qoff = ((size_t)b * Sn + s0) * En;
    const size_t koff = ((size_t)b * Sn + t0) * En;
    float acc[4][8][4] = {};
    hmma_pipe(g_qhi + qoff, g_khi + koff, En, En, En, acc);

    __shared__ float rsum[128];
    if (tid < 128) rsum[tid] = 0.0f;
    __syncthreads();
    const int w = tid >> 5, l = tid & 31;
    const int wm = (w & 1) * 64, wn = (w >> 1) * 64;
#pragma unroll
    for (int mi = 0; mi < 4; mi++) {
#pragma unroll
        for (int rh = 0; rh < 2; rh++) {
            const int lr = wm + mi * 16 + (l >> 2) + rh * 8;
            const size_t grow = (size_t)b * Sn + s0 + lr;
            const float* mrow = mask + grow * Sn + t0;
            __half* dh = g_dhi + grow * Sn + t0;
            float part = 0.0f;
#pragma unroll
            for (int ni = 0; ni < 8; ni++) {
                const int col = wn + ni * 8 + (l & 3) * 2;
                const float2 m2 = *(const float2*)(mrow + col);
                const float mc0 = fminf(fmaxf(m2.x, 0.0f), 1.0f);
                const float mc1 = fminf(fmaxf(m2.y, 0.0f), 1.0f);
                const __half h0 = __float2half_rn(__expf(acc[mi][ni][rh * 2]) * mc0);
                const __half h1 = __float2half_rn(__expf(acc[mi][ni][rh * 2 + 1]) * mc1);
                part += __half2float(h0) + __half2float(h1);
                *(uint32_t*)(dh + col) = h2u(h0, h1);
            }
            part += __shfl_xor_sync(0xFFFFFFFF, part, 1);
            part += __shfl_xor_sync(0xFFFFFFFF, part, 2);
            if ((l & 3) == 0) atomicAdd(&rsum[lr], part);
        }
    }
    __syncthreads();
    if (tid < 128) atomicAdd(&g_rowsum[(size_t)b * Sn + s0 + tid], rsum[tid]);
}

// grid = (e-blocks = En/256 = 2, s-blocks = 16, b = 8)
__global__ __launch_bounds__(256, 1) void outgemm_h(float* __restrict__ out) {
    const int b = blockIdx.z;
    const int s0 = blockIdx.y * 128;
    const int e0 = blockIdx.x * 256;
    const size_t doff = ((size_t)b * Sn + s0) * Sn;
    const size_t voff = ((size_t)b * En + e0) * Sn;
    float acc[4][8][4] = {};
    hmma_pipe(g_dhi + doff, g_vThi + voff, Sn, Sn, Sn, acc);
    const int tid = threadIdx.x;
    const int w = tid >> 5, l = tid & 31;
    const int wm = (w & 1) * 64, wn = (w >> 1) * 64;
#pragma unroll
    for (int mi = 0; mi < 4; mi++) {
#pragma unroll
        for (int rh = 0; rh < 2; rh++) {
            const int lr = wm + mi * 16 + (l >> 2) + rh * 8;
            const size_t grow = (size_t)b * Sn + s0 + lr;
            const float inv = 1.0f / (g_rowsum[grow] + 1e-10f);
            float* orow = out + grow * En + e0;
#pragma unroll
            for (int ni = 0; ni < 8; ni++) {
                const int col = wn + ni * 8 + (l & 3) * 2;
                *(float2*)(orow + col) =
                    make_float2(acc[mi][ni][rh * 2] * inv,
                                acc[mi][ni][rh * 2 + 1] * inv);
            }
        }
    }
}

// ---------------------------------------------------------------------------
extern "C" void kernel_launch(void* const* d_in, const int* in_sizes, int n_in,
                              void* d_out, int out_size) {
    const int* key_seq = (const int*)d_in[0];
    const int* value_seq = (const int*)d_in[1];
    const float* hidden = (const float*)d_in[2];
    const float* mask = (const float*)d_in[3];
    const float* key_emb = (const float*)d_in[5];
    const float* value_emb = (const float*)d_in[6];
    const float* weight = (const float*)d_in[7];
    float* out = (float*)d_out;

    cudaFuncSetAttribute(qgemm_h, cudaFuncAttributeMaxDynamicSharedMemorySize,
                         SMEM_GB);
    cudaFuncSetAttribute(scores_h, cudaFuncAttributeMaxDynamicSharedMemorySize,
                         SMEM_GB);
    cudaFuncSetAttribute(outgemm_h, cudaFuncAttributeMaxDynamicSharedMemorySize,
                         SMEM_GB);

    prep_hw<<<HID_BLOCKS + W_BLOCKS, 256>>>(hidden, weight);
    gather_k<<<BSn, 128>>>(key_seq, key_emb);
    gather_vT<<<dim3(Sn / 64, En / 64, Bn), 256>>>(value_seq, value_emb);
    qgemm_h<<<dim3(En / 256, BSn / 128), 256, SMEM_GB>>>();
    scores_h<<<dim3(Sn / 256, Sn / 128, Bn), 256, SMEM_GB>>>(mask);
    outgemm_h<<<dim3(En / 256, Sn / 128, Bn), 256, SMEM_GB>>>(out);
}

// round 15
// speedup vs baseline: 1.8202x; 1.0889x over previous
#include <cuda_runtime.h>
#include <cuda_fp16.h>
#include <math.h>
#include <stdint.h>

#define Bn 8
#define Sn 2048
#define En 512
#define BSn (Bn * Sn)  // 16384

__device__ __constant__ float c_inv_scale = 0.044194173824159216f; // 1/sqrt(512)

// ---------------- scratch ---------------------------------------------------
__device__ __half g_hhi[(size_t)BSn * En];
__device__ __half g_wThi[(size_t)En * En];       // [e_out][e_in]
__device__ __half g_qhi[(size_t)BSn * En];       // pre-scaled by 1/sqrt(E)
__device__ __half g_khi[(size_t)BSn * En];
__device__ __half g_vThi[(size_t)Bn * En * Sn];  // [b][e][t]
__device__ __half g_dhi[(size_t)Bn * Sn * Sn];   // delta fp16 [b*S+s][t]
__device__ float g_rowsum[BSn];

// ---------------- helpers ----------------------------------------------------
__device__ __forceinline__ uint32_t smem_u32(const void* p) {
    uint32_t a;
    asm("{ .reg .u64 t; cvta.to.shared.u64 t, %1; cvt.u32.u64 %0, t; }"
        : "=r"(a) : "l"(p));
    return a;
}
__device__ __forceinline__ void ldsm_x4(uint32_t (&r)[4], uint32_t addr) {
    asm volatile(
        "ldmatrix.sync.aligned.m8n8.x4.shared.b16 {%0,%1,%2,%3}, [%4];"
        : "=r"(r[0]), "=r"(r[1]), "=r"(r[2]), "=r"(r[3]) : "r"(addr));
}
__device__ __forceinline__ void mma16816(float (&d)[4], const uint32_t (&a)[4],
                                         uint32_t b0, uint32_t b1) {
    asm volatile(
        "mma.sync.aligned.m16n8k16.row.col.f32.f16.f16.f32 "
        "{%0,%1,%2,%3}, {%4,%5,%6,%7}, {%8,%9}, {%0,%1,%2,%3};"
        : "+f"(d[0]), "+f"(d[1]), "+f"(d[2]), "+f"(d[3])
        : "r"(a[0]), "r"(a[1]), "r"(a[2]), "r"(a[3]), "r"(b0), "r"(b1));
}
#define CPA16(dst, src) \
    asm volatile("cp.async.ca.shared.global [%0], [%1], 16;" \
                 :: "r"(dst), "l"(src) : "memory")
#define CPA_COMMIT() asm volatile("cp.async.commit_group;" ::: "memory")
#define CPA_WAIT2() asm volatile("cp.async.wait_group 2;" ::: "memory")
#define CPA_WAIT1() asm volatile("cp.async.wait_group 1;" ::: "memory")
#define CPA_WAIT0() asm volatile("cp.async.wait_group 0;" ::: "memory")

__device__ __forceinline__ uint32_t h2u(__half a, __half b) {
    __half2 p = __halves2half2(a, b);
    return *reinterpret_cast<uint32_t*>(&p);
}

// ---------------------------------------------------------------------------
// 4-stage cp.async pipelined fp16 HMMA mainloop, block tile 128x256,
// 512 THREADS (16 warps = 4/SMSP), warp grid 4(M)x4(N), warp tile 32x64.
// K-chunk 32. Same smem layout as the 256-thread R11/R14 version.
// ---------------------------------------------------------------------------
#define PAD 40
#define TILEA 10240
#define TILEBB 20480
#define ST (TILEA + TILEBB)   // 30720
#define STAGES 4
#define SMEM_GB (STAGES * ST) // 122880

__device__ __forceinline__ void hmma_pipe(
    const __half* __restrict__ A, const __half* __restrict__ B, int lda,
    int ldb, int ktot, float (&acc)[2][8][4]) {
    extern __shared__ __align__(16) __half sm[];
    const uint32_t s0 = smem_u32(sm);

    const int tid = threadIdx.x;
    const int w = tid >> 5, l = tid & 31;
    const int wm = (w & 3) * 32, wn = (w >> 2) * 64;
    const int lrow = l & 7, quad = l >> 3;

    // loaders (512 threads): A: 4 thr/row x 16B (128 rows x 64B);
    //                        B: 2 thr/row x 32B (256 rows x 64B)
    const int arow = tid >> 2;
    const int aseg = (tid & 3) * 8;  // halves
    const uint32_t adst = (uint32_t)(arow * PAD + aseg) * 2;
    const int brow = tid >> 1;
    const int bseg = (tid & 1) * 16;  // halves
    const uint32_t bdst = TILEA + (uint32_t)(brow * PAD + bseg) * 2;

    const int nck = ktot / 32;

    // ks=0 base addresses; ks=1 = +32 bytes
    uint32_t a_addr[2], b_addr[4];
#pragma unroll
    for (int mi = 0; mi < 2; mi++)
        a_addr[mi] = s0 + ((wm + mi * 16 + (quad & 1) * 8 + lrow) * PAD +
                           (quad >> 1) * 8) * 2;
#pragma unroll
    for (int bi = 0; bi < 4; bi++)
        b_addr[bi] = s0 + TILEA +
                     ((wn + bi * 16 + (quad >> 1) * 8 + lrow) * PAD +
                      (quad & 1) * 8) * 2;

    auto load_chunk = [&](int c) {
        const uint32_t base = s0 + (uint32_t)(c & (STAGES - 1)) * ST;
        const __half* pa = A + (size_t)arow * lda + c * 32 + aseg;
        CPA16(base + adst, pa);
        const __half* pb = B + (size_t)brow * ldb + c * 32 + bseg;
        CPA16(base + bdst, pb);
        CPA16(base + bdst + 16, pb + 8);
    };

    load_chunk(0);
    CPA_COMMIT();
    load_chunk(1);
    CPA_COMMIT();
    load_chunk(2);
    CPA_COMMIT();

    for (int c = 0; c < nck; c++) {
        if (c <= nck - 3) {
            CPA_WAIT2();
        } else if (c == nck - 2) {
            CPA_WAIT1();
        } else {
            CPA_WAIT0();
        }
        __syncthreads();
        if (c + 3 < nck) {
            load_chunk(c + 3);
            CPA_COMMIT();
        }
        const uint32_t boff = (uint32_t)(c & (STAGES - 1)) * ST;
#pragma unroll
        for (int ks = 0; ks < 2; ks++) {
            uint32_t ah[2][4], bh[4][4];
#pragma unroll
            for (int mi = 0; mi < 2; mi++)
                ldsm_x4(ah[mi], a_addr[mi] + boff + ks * 32);
#pragma unroll
            for (int bi = 0; bi < 4; bi++)
                ldsm_x4(bh[bi], b_addr[bi] + boff + ks * 32);
#pragma unroll
            for (int mi = 0; mi < 2; mi++)
#pragma unroll
                for (int ni = 0; ni < 8; ni++)
                    mma16816(acc[mi][ni], ah[mi], bh[ni >> 1][(ni & 1) * 2],
                             bh[ni >> 1][(ni & 1) * 2 + 1]);
        }
    }
}

// ---------------------------------------------------------------------------
// Prep kernels (R14 layout, proven)
// ---------------------------------------------------------------------------
#define HID_BLOCKS ((int)((size_t)BSn * En / 8 / 256))  // 4096
#define W_BLOCKS (En * En / 256)                        // 1024

__global__ __launch_bounds__(256) void prep_hw(const float* __restrict__ h,
                                               const float* __restrict__ W) {
    const int bid = blockIdx.x;
    if (bid < HID_BLOCKS) {
        const size_t i8 = ((size_t)bid * 256 + threadIdx.x) * 8;
        const float4 f0 = *(const float4*)(h + i8);
        const float4 f1 = *(const float4*)(h + i8 + 4);
        *(uint4*)(g_hhi + i8) = make_uint4(
            h2u(__float2half_rn(f0.x), __float2half_rn(f0.y)),
            h2u(__float2half_rn(f0.z), __float2half_rn(f0.w)),
            h2u(__float2half_rn(f1.x), __float2half_rn(f1.y)),
            h2u(__float2half_rn(f1.z), __float2half_rn(f1.w)));
    } else {
        const int idx = (bid - HID_BLOCKS) * 256 + threadIdx.x;
        const int eo = idx >> 9;
        const int ei = idx & 511;
        g_wThi[idx] = __float2half_rn(W[(size_t)ei * En + eo]);
    }
}

__global__ __launch_bounds__(128) void gather_k(const int* __restrict__ kseq,
                                                const float* __restrict__ kemb) {
    const int row = blockIdx.x;
    const int t = threadIdx.x;
    if (t == 0) g_rowsum[row] = 0.0f;
    const int ki = kseq[row];
    const float4 f = *(const float4*)(kemb + (size_t)ki * En + t * 4);
    *(uint2*)(g_khi + (size_t)row * En + t * 4) =
        make_uint2(h2u(__float2half_rn(f.x), __float2half_rn(f.y)),
                   h2u(__float2half_rn(f.z), __float2half_rn(f.w)));
}

__global__ __launch_bounds__(256) void gather_vT(const int* __restrict__ vseq,
                                                 const float* __restrict__ vemb) {
    __shared__ float tile[64][65];
    const int b = blockIdx.z;
    const int e0 = blockIdx.y * 64;
    const int t0 = blockIdx.x * 64;
    const int tid = threadIdx.x;
    const int tr = tid >> 4;
    const int tc = (tid & 15) * 4;
#pragma unroll
    for (int rr = 0; rr < 4; rr++) {
        const int tl = tr + rr * 16;
        const int vi = vseq[b * Sn + t0 + tl];
        const float4 f = *(const float4*)(vemb + (size_t)vi * En + e0 + tc);
        tile[tl][tc + 0] = f.x;
        tile[tl][tc + 1] = f.y;
        tile[tl][tc + 2] = f.z;
        tile[tl][tc + 3] = f.w;
    }
    __syncthreads();
    const int er = tid >> 3;
    const int seg = (tid & 7) * 8;
#pragma unroll
    for (int pp = 0; pp < 2; pp++) {
        const int el = er + pp * 32;
        __half hh[8];
#pragma unroll
        for (int j = 0; j < 8; j++) hh[j] = __float2half_rn(tile[seg + j][el]);
        const size_t o = ((size_t)b * En + e0 + el) * Sn + t0 + seg;
        *(uint4*)(g_vThi + o) = make_uint4(h2u(hh[0], hh[1]), h2u(hh[2], hh[3]),
                                           h2u(hh[4], hh[5]), h2u(hh[6], hh[7]));
    }
}

// ---------------------------------------------------------------------------
// GEMM kernels (512 threads, 1 CTA/SM, dynamic smem SMEM_GB)
// ---------------------------------------------------------------------------
__global__ __launch_bounds__(512, 1) void qgemm_h() {
    const int s0 = blockIdx.y * 128;
    const int n0 = blockIdx.x * 256;
    float acc[2][8][4] = {};
    hmma_pipe(g_hhi + (size_t)s0 * En, g_wThi + (size_t)n0 * En, En, En, En,
              acc);
    const int tid = threadIdx.x;
    const int w = tid >> 5, l = tid & 31;
    const int wm = (w & 3) * 32, wn = (w >> 2) * 64;
#pragma unroll
    for (int mi = 0; mi < 2; mi++) {
#pragma unroll
        for (int rh = 0; rh < 2; rh++) {
            const int row = s0 + wm + mi * 16 + (l >> 2) + rh * 8;
#pragma unroll
            for (int ni = 0; ni < 8; ni++) {
                const int col = n0 + wn + ni * 8 + (l & 3) * 2;
                const size_t o = (size_t)row * En + col;
                *(uint32_t*)(g_qhi + o) =
                    h2u(__float2half_rn(acc[mi][ni][rh * 2] * c_inv_scale),
                        __float2half_rn(acc[mi][ni][rh * 2 + 1] * c_inv_scale));
            }
        }
    }
}

// grid = (t-blocks = Sn/256 = 8, s-blocks = 16, b = 8)
__global__ __launch_bounds__(512, 1) void scores_h(const float* __restrict__ mask) {
    const int b = blockIdx.z;
    const int s0 = blockIdx.y * 128;
    const int t0 = blockIdx.x * 256;
    const int tid = threadIdx.x;
    const size_t qoff = ((size_t)b * Sn + s0) * En;
    const size_t koff = ((size_t)b * Sn + t0) * En;
    float acc[2][8][4] = {};
    hmma_pipe(g_qhi + qoff, g_khi + koff, En, En, En, acc);

    __shared__ float rsum[128];
    if (tid < 128) rsum[tid] = 0.0f;
    __syncthreads();
    const int w = tid >> 5, l = tid & 31;
    const int wm = (w & 3) * 32, wn = (w >> 2) * 64;
#pragma unroll
    for (int mi = 0; mi < 2; mi++) {
#pragma unroll
        for (int rh = 0; rh < 2; rh++) {
            const int lr = wm + mi * 16 + (l >> 2) + rh * 8;
            const size_t grow = (size_t)b * Sn + s0 + lr;
            const float* mrow = mask + grow * Sn + t0;
            __half* dh = g_dhi + grow * Sn + t0;
            float part = 0.0f;
#pragma unroll
            for (int ni = 0; ni < 8; ni++) {
                const int col = wn + ni * 8 + (l & 3) * 2;
                const float2 m2 = *(const float2*)(mrow + col);
                const float mc0 = fminf(fmaxf(m2.x, 0.0f), 1.0f);
                const float mc1 = fminf(fmaxf(m2.y, 0.0f), 1.0f);
                const __half h0 = __float2half_rn(__expf(acc[mi][ni][rh * 2]) * mc0);
                const __half h1 = __float2half_rn(__expf(acc[mi][ni][rh * 2 + 1]) * mc1);
                part += __half2float(h0) + __half2float(h1);
                *(uint32_t*)(dh + col) = h2u(h0, h1);
            }
            part += __shfl_xor_sync(0xFFFFFFFF, part, 1);
            part += __shfl_xor_sync(0xFFFFFFFF, part, 2);
            if ((l & 3) == 0) atomicAdd(&rsum[lr], part);
        }
    }
    __syncthreads();
    if (tid < 128) atomicAdd(&g_rowsum[(size_t)b * Sn + s0 + tid], rsum[tid]);
}

// grid = (e-blocks = En/256 = 2, s-blocks = 16, b = 8)
__global__ __launch_bounds__(512, 1) void outgemm_h(float* __restrict__ out) {
    const int b = blockIdx.z;
    const int s0 = blockIdx.y * 128;
    const int e0 = blockIdx.x * 256;
    const size_t doff = ((size_t)b * Sn + s0) * Sn;
    const size_t voff = ((size_t)b * En + e0) * Sn;
    float acc[2][8][4] = {};
    hmma_pipe(g_dhi + doff, g_vThi + voff, Sn, Sn, Sn, acc);
    const int tid = threadIdx.x;
    const int w = tid >> 5, l = tid & 31;
    const int wm = (w & 3) * 32, wn = (w >> 2) * 64;
#pragma unroll
    for (int mi = 0; mi < 2; mi++) {
#pragma unroll
        for (int rh = 0; rh < 2; rh++) {
            const int lr = wm + mi * 16 + (l >> 2) + rh * 8;
            const size_t grow = (size_t)b * Sn + s0 + lr;
            const float inv = 1.0f / (g_rowsum[grow] + 1e-10f);
            float* orow = out + grow * En + e0;
#pragma unroll
            for (int ni = 0; ni < 8; ni++) {
                const int col = wn + ni * 8 + (l & 3) * 2;
                *(float2*)(orow + col) =
                    make_float2(acc[mi][ni][rh * 2] * inv,
                                acc[mi][ni][rh * 2 + 1] * inv);
            }
        }
    }
}

// ---------------------------------------------------------------------------
extern "C" void kernel_launch(void* const* d_in, const int* in_sizes, int n_in,
                              void* d_out, int out_size) {
    const int* key_seq = (const int*)d_in[0];
    const int* value_seq = (const int*)d_in[1];
    const float* hidden = (const float*)d_in[2];
    const float* mask = (const float*)d_in[3];
    const float* key_emb = (const float*)d_in[5];
    const float* value_emb = (const float*)d_in[6];
    const float* weight = (const float*)d_in[7];
    float* out = (float*)d_out;

    cudaFuncSetAttribute(qgemm_h, cudaFuncAttributeMaxDynamicSharedMemorySize,
                         SMEM_GB);
    cudaFuncSetAttribute(scores_h, cudaFuncAttributeMaxDynamicSharedMemorySize,
                         SMEM_GB);
    cudaFuncSetAttribute(outgemm_h, cudaFuncAttributeMaxDynamicSharedMemorySize,
                         SMEM_GB);

    prep_hw<<<HID_BLOCKS + W_BLOCKS, 256>>>(hidden, weight);
    gather_k<<<BSn, 128>>>(key_seq, key_emb);
    gather_vT<<<dim3(Sn / 64, En / 64, Bn), 256>>>(value_seq, value_emb);
    qgemm_h<<<dim3(En / 256, BSn / 128), 512, SMEM_GB>>>();
    scores_h<<<dim3(Sn / 256, Sn / 128, Bn), 512, SMEM_GB>>>(mask);
    outgemm_h<<<dim3(En / 256, Sn / 128, Bn), 512, SMEM_GB>>>(out);
}

// round 16
// speedup vs baseline: 1.8406x; 1.0112x over previous
#include <cuda_runtime.h>
#include <cuda_fp16.h>
#include <math.h>
#include <stdint.h>

#define Bn 8
#define Sn 2048
#define En 512
#define BSn (Bn * Sn)  // 16384

__device__ __constant__ float c_inv_scale = 0.044194173824159216f; // 1/sqrt(512)

// ---------------- scratch ---------------------------------------------------
__device__ __half g_hhi[(size_t)BSn * En];
__device__ __half g_wThi[(size_t)En * En];       // [e_out][e_in]
__device__ __half g_qhi[(size_t)BSn * En];       // pre-scaled by 1/sqrt(E)
__device__ __half g_khi[(size_t)BSn * En];
__device__ __half g_vThi[(size_t)Bn * En * Sn];  // [b][e][t]
__device__ __half g_dhi[(size_t)Bn * Sn * Sn];   // delta fp16 [b*S+s][t]
__device__ float g_rowsum[BSn];

// ---------------- helpers ----------------------------------------------------
__device__ __forceinline__ uint32_t smem_u32(const void* p) {
    uint32_t a;
    asm("{ .reg .u64 t; cvta.to.shared.u64 t, %1; cvt.u32.u64 %0, t; }"
        : "=r"(a) : "l"(p));
    return a;
}
__device__ __forceinline__ void ldsm_x4(uint32_t (&r)[4], uint32_t addr) {
    asm volatile(
        "ldmatrix.sync.aligned.m8n8.x4.shared.b16 {%0,%1,%2,%3}, [%4];"
        : "=r"(r[0]), "=r"(r[1]), "=r"(r[2]), "=r"(r[3]) : "r"(addr));
}
__device__ __forceinline__ void mma16816(float (&d)[4], const uint32_t (&a)[4],
                                         uint32_t b0, uint32_t b1) {
    asm volatile(
        "mma.sync.aligned.m16n8k16.row.col.f32.f16.f16.f32 "
        "{%0,%1,%2,%3}, {%4,%5,%6,%7}, {%8,%9}, {%0,%1,%2,%3};"
        : "+f"(d[0]), "+f"(d[1]), "+f"(d[2]), "+f"(d[3])
        : "r"(a[0]), "r"(a[1]), "r"(a[2]), "r"(a[3]), "r"(b0), "r"(b1));
}
#define CPA16(dst, src) \
    asm volatile("cp.async.ca.shared.global [%0], [%1], 16;" \
                 :: "r"(dst), "l"(src) : "memory")
#define CPA_COMMIT() asm volatile("cp.async.commit_group;" ::: "memory")
#define CPA_WAIT1() asm volatile("cp.async.wait_group 1;" ::: "memory")
#define CPA_WAIT0() asm volatile("cp.async.wait_group 0;" ::: "memory")

__device__ __forceinline__ uint32_t h2u(__half a, __half b) {
    __half2 p = __halves2half2(a, b);
    return *reinterpret_cast<uint32_t*>(&p);
}

// ---------------------------------------------------------------------------
// 3-stage cp.async pipelined fp16 HMMA mainloop, block tile 128x256,
// K-CHUNK 64, 512 threads (16 warps = 4/SMSP), warp grid 4(M)x4(N),
// warp tile 32x64. smem/stage: A 128x72h (18432 B) + B 256x72h (36864 B).
// Halves the per-chunk barrier/wait overhead vs K-chunk 32.
// ---------------------------------------------------------------------------
#define PAD 72
#define TILEA 18432
#define TILEBB 36864
#define ST (TILEA + TILEBB)   // 55296
#define STAGES 3
#define SMEM_GB (STAGES * ST) // 165888

__device__ __forceinline__ void hmma_pipe(
    const __half* __restrict__ A, const __half* __restrict__ B, int lda,
    int ldb, int ktot, float (&acc)[2][8][4]) {
    extern __shared__ __align__(16) __half sm[];
    const uint32_t s0 = smem_u32(sm);

    const int tid = threadIdx.x;
    const int w = tid >> 5, l = tid & 31;
    const int wm = (w & 3) * 32, wn = (w >> 2) * 64;
    const int lrow = l & 7, quad = l >> 3;

    // loaders (512 threads, 64-half rows):
    //   A: 4 thr/row x 32B (128 rows); B: 2 thr/row x 64B (256 rows)
    const int arow = tid >> 2;
    const int aseg = (tid & 3) * 16;  // halves
    const uint32_t adst = (uint32_t)(arow * PAD + aseg) * 2;
    const int brow = tid >> 1;
    const int bseg = (tid & 1) * 32;  // halves
    const uint32_t bdst = TILEA + (uint32_t)(brow * PAD + bseg) * 2;

    const int nck = ktot / 64;

    // ks=0 base addresses; ks=1..3 add +32 bytes each
    uint32_t a_addr[2], b_addr[4];
#pragma unroll
    for (int mi = 0; mi < 2; mi++)
        a_addr[mi] = s0 + ((wm + mi * 16 + (quad & 1) * 8 + lrow) * PAD +
                           (quad >> 1) * 8) * 2;
#pragma unroll
    for (int bi = 0; bi < 4; bi++)
        b_addr[bi] = s0 + TILEA +
                     ((wn + bi * 16 + (quad >> 1) * 8 + lrow) * PAD +
                      (quad & 1) * 8) * 2;

    auto load_chunk = [&](int c, int stg) {
        const uint32_t base = s0 + (uint32_t)stg * ST;
        const __half* pa = A + (size_t)arow * lda + c * 64 + aseg;
        CPA16(base + adst, pa);
        CPA16(base + adst + 16, pa + 8);
        const __half* pb = B + (size_t)brow * ldb + c * 64 + bseg;
        CPA16(base + bdst, pb);
        CPA16(base + bdst + 16, pb + 8);
        CPA16(base + bdst + 32, pb + 16);
        CPA16(base + bdst + 48, pb + 24);
    };

    load_chunk(0, 0);
    CPA_COMMIT();
    load_chunk(1, 1);
    CPA_COMMIT();

    int cons = 0;  // stage being consumed
    int ldst = 2;  // stage to load next
    for (int c = 0; c < nck; c++) {
        if (c < nck - 1) {
            CPA_WAIT1();
        } else {
            CPA_WAIT0();
        }
        __syncthreads();
        if (c + 2 < nck) {
            load_chunk(c + 2, ldst);
            CPA_COMMIT();
            if (++ldst == STAGES) ldst = 0;
        }
        const uint32_t boff = (uint32_t)cons * ST;
        if (++cons == STAGES) cons = 0;
#pragma unroll
        for (int ks = 0; ks < 4; ks++) {
            uint32_t ah[2][4], bh[4][4];
#pragma unroll
            for (int mi = 0; mi < 2; mi++)
                ldsm_x4(ah[mi], a_addr[mi] + boff + ks * 32);
#pragma unroll
            for (int bi = 0; bi < 4; bi++)
                ldsm_x4(bh[bi], b_addr[bi] + boff + ks * 32);
#pragma unroll
            for (int mi = 0; mi < 2; mi++)
#pragma unroll
                for (int ni = 0; ni < 8; ni++)
                    mma16816(acc[mi][ni], ah[mi], bh[ni >> 1][(ni & 1) * 2],
                             bh[ni >> 1][(ni & 1) * 2 + 1]);
        }
    }
}

// ---------------------------------------------------------------------------
// Prep kernels (proven layout)
// ---------------------------------------------------------------------------
#define HID_BLOCKS ((int)((size_t)BSn * En / 8 / 256))  // 4096
#define W_BLOCKS (En * En / 256)                        // 1024

__global__ __launch_bounds__(256) void prep_hw(const float* __restrict__ h,
                                               const float* __restrict__ W) {
    const int bid = blockIdx.x;
    if (bid < HID_BLOCKS) {
        const size_t i8 = ((size_t)bid * 256 + threadIdx.x) * 8;
        const float4 f0 = *(const float4*)(h + i8);
        const float4 f1 = *(const float4*)(h + i8 + 4);
        *(uint4*)(g_hhi + i8) = make_uint4(
            h2u(__float2half_rn(f0.x), __float2half_rn(f0.y)),
            h2u(__float2half_rn(f0.z), __float2half_rn(f0.w)),
            h2u(__float2half_rn(f1.x), __float2half_rn(f1.y)),
            h2u(__float2half_rn(f1.z), __float2half_rn(f1.w)));
    } else {
        const int idx = (bid - HID_BLOCKS) * 256 + threadIdx.x;
        const int eo = idx >> 9;
        const int ei = idx & 511;
        g_wThi[idx] = __float2half_rn(W[(size_t)ei * En + eo]);
    }
}

__global__ __launch_bounds__(128) void gather_k(const int* __restrict__ kseq,
                                                const float* __restrict__ kemb) {
    const int row = blockIdx.x;
    const int t = threadIdx.x;
    if (t == 0) g_rowsum[row] = 0.0f;
    const int ki = kseq[row];
    const float4 f = *(const float4*)(kemb + (size_t)ki * En + t * 4);
    *(uint2*)(g_khi + (size_t)row * En + t * 4) =
        make_uint2(h2u(__float2half_rn(f.x), __float2half_rn(f.y)),
                   h2u(__float2half_rn(f.z), __float2half_rn(f.w)));
}

__global__ __launch_bounds__(256) void gather_vT(const int* __restrict__ vseq,
                                                 const float* __restrict__ vemb) {
    __shared__ float tile[64][65];
    const int b = blockIdx.z;
    const int e0 = blockIdx.y * 64;
    const int t0 = blockIdx.x * 64;
    const int tid = threadIdx.x;
    const int tr = tid >> 4;
    const int tc = (tid & 15) * 4;
#pragma unroll
    for (int rr = 0; rr < 4; rr++) {
        const int tl = tr + rr * 16;
        const int vi = vseq[b * Sn + t0 + tl];
        const float4 f = *(const float4*)(vemb + (size_t)vi * En + e0 + tc);
        tile[tl][tc + 0] = f.x;
        tile[tl][tc + 1] = f.y;
        tile[tl][tc + 2] = f.z;
        tile[tl][tc + 3] = f.w;
    }
    __syncthreads();
    const int er = tid >> 3;
    const int seg = (tid & 7) * 8;
#pragma unroll
    for (int pp = 0; pp < 2; pp++) {
        const int el = er + pp * 32;
        __half hh[8];
#pragma unroll
        for (int j = 0; j < 8; j++) hh[j] = __float2half_rn(tile[seg + j][el]);
        const size_t o = ((size_t)b * En + e0 + el) * Sn + t0 + seg;
        *(uint4*)(g_vThi + o) = make_uint4(h2u(hh[0], hh[1]), h2u(hh[2], hh[3]),
                                           h2u(hh[4], hh[5]), h2u(hh[6], hh[7]));
    }
}

// ---------------------------------------------------------------------------
// GEMM kernels (512 threads, 1 CTA/SM, dynamic smem SMEM_GB)
// ---------------------------------------------------------------------------
__global__ __launch_bounds__(512, 1) void qgemm_h() {
    const int s0 = blockIdx.y * 128;
    const int n0 = blockIdx.x * 256;
    float acc[2][8][4] = {};
    hmma_pipe(g_hhi + (size_t)s0 * En, g_wThi + (size_t)n0 * En, En, En, En,
              acc);
    const int tid = threadIdx.x;
    const int w = tid >> 5, l = tid & 31;
    const int wm = (w & 3) * 32, wn = (w >> 2) * 64;
#pragma unroll
    for (int mi = 0; mi < 2; mi++) {
#pragma unroll
        for (int rh = 0; rh < 2; rh++) {
            const int row = s0 + wm + mi * 16 + (l >> 2) + rh * 8;
#pragma unroll
            for (int ni = 0; ni < 8; ni++) {
                const int col = n0 + wn + ni * 8 + (l & 3) * 2;
                const size_t o = (size_t)row * En + col;
                *(uint32_t*)(g_qhi + o) =
                    h2u(__float2half_rn(acc[mi][ni][rh * 2] * c_inv_scale),
                        __float2half_rn(acc[mi][ni][rh * 2 + 1] * c_inv_scale));
            }
        }
    }
}

// grid = (t-blocks = Sn/256 = 8, s-blocks = 16, b = 8)
__global__ __launch_bounds__(512, 1) void scores_h(const float* __restrict__ mask) {
    const int b = blockIdx.z;
    const int s0 = blockIdx.y * 128;
    const int t0 = blockIdx.x * 256;
    const int tid = threadIdx.x;
    const size_t qoff = ((size_t)b * Sn + s0) * En;
    const size_t koff = ((size_t)b * Sn + t0) * En;
    float acc[2][8][4] = {};
    hmma_pipe(g_qhi + qoff, g_khi + koff, En, En, En, acc);

    __shared__ float rsum[128];
    if (tid < 128) rsum[tid] = 0.0f;
    __syncthreads();
    const int w = tid >> 5, l = tid & 31;
    const int wm = (w & 3) * 32, wn = (w >> 2) * 64;
#pragma unroll
    for (int mi = 0; mi < 2; mi++) {
#pragma unroll
        for (int rh = 0; rh < 2; rh++) {
            const int lr = wm + mi * 16 + (l >> 2) + rh * 8;
            const size_t grow = (size_t)b * Sn + s0 + lr;
            const float* mrow = mask + grow * Sn + t0;
            __half* dh = g_dhi + grow * Sn + t0;
            float part = 0.0f;
#pragma unroll
            for (int ni = 0; ni < 8; ni++) {
                const int col = wn + ni * 8 + (l & 3) * 2;
                const float2 m2 = *(const float2*)(mrow + col);
                const float mc0 = fminf(fmaxf(m2.x, 0.0f), 1.0f);
                const float mc1 = fminf(fmaxf(m2.y, 0.0f), 1.0f);
                const __half h0 = __float2half_rn(__expf(acc[mi][ni][rh * 2]) * mc0);
                const __half h1 = __float2half_rn(__expf(acc[mi][ni][rh * 2 + 1]) * mc1);
                part += __half2float(h0) + __half2float(h1);
                *(uint32_t*)(dh + col) = h2u(h0, h1);
            }
            part += __shfl_xor_sync(0xFFFFFFFF, part, 1);
            part += __shfl_xor_sync(0xFFFFFFFF, part, 2);
            if ((l & 3) == 0) atomicAdd(&rsum[lr], part);
        }
    }
    __syncthreads();
    if (tid < 128) atomicAdd(&g_rowsum[(size_t)b * Sn + s0 + tid], rsum[tid]);
}

// grid = (e-blocks = En/256 = 2, s-blocks = 16, b = 8)
__global__ __launch_bounds__(512, 1) void outgemm_h(float* __restrict__ out) {
    const int b = blockIdx.z;
    const int s0 = blockIdx.y * 128;
    const int e0 = blockIdx.x * 256;
    const size_t doff = ((size_t)b * Sn + s0) * Sn;
    const size_t voff = ((size_t)b * En + e0) * Sn;
    float acc[2][8][4] = {};
    hmma_pipe(g_dhi + doff, g_vThi + voff, Sn, Sn, Sn, acc);
    const int tid = threadIdx.x;
    const int w = tid >> 5, l = tid & 31;
    const int wm = (w & 3) * 32, wn = (w >> 2) * 64;
#pragma unroll
    for (int mi = 0; mi < 2; mi++) {
#pragma unroll
        for (int rh = 0; rh < 2; rh++) {
            const int lr = wm + mi * 16 + (l >> 2) + rh * 8;
            const size_t grow = (size_t)b * Sn + s0 + lr;
            const float inv = 1.0f / (g_rowsum[grow] + 1e-10f);
            float* orow = out + grow * En + e0;
#pragma unroll
            for (int ni = 0; ni < 8; ni++) {
                const int col = wn + ni * 8 + (l & 3) * 2;
                *(float2*)(orow + col) =
                    make_float2(acc[mi][ni][rh * 2] * inv,
                                acc[mi][ni][rh * 2 + 1] * inv);
            }
        }
    }
}

// ---------------------------------------------------------------------------
extern "C" void kernel_launch(void* const* d_in, const int* in_sizes, int n_in,
                              void* d_out, int out_size) {
    const int* key_seq = (const int*)d_in[0];
    const int* value_seq = (const int*)d_in[1];
    const float* hidden = (const float*)d_in[2];
    const float* mask = (const float*)d_in[3];
    const float* key_emb = (const float*)d_in[5];
    const float* value_emb = (const float*)d_in[6];
    const float* weight = (const float*)d_in[7];
    float* out = (float*)d_out;

    cudaFuncSetAttribute(qgemm_h, cudaFuncAttributeMaxDynamicSharedMemorySize,
                         SMEM_GB);
    cudaFuncSetAttribute(scores_h, cudaFuncAttributeMaxDynamicSharedMemorySize,
                         SMEM_GB);
    cudaFuncSetAttribute(outgemm_h, cudaFuncAttributeMaxDynamicSharedMemorySize,
                         SMEM_GB);

    prep_hw<<<HID_BLOCKS + W_BLOCKS, 256>>>(hidden, weight);
    gather_k<<<BSn, 128>>>(key_seq, key_emb);
    gather_vT<<<dim3(Sn / 64, En / 64, Bn), 256>>>(value_seq, value_emb);
    qgemm_h<<<dim3(En / 256, BSn / 128), 512, SMEM_GB>>>();
    scores_h<<<dim3(Sn / 256, Sn / 128, Bn), 512, SMEM_GB>>>(mask);
    outgemm_h<<<dim3(En / 256, Sn / 128, Bn), 512, SMEM_GB>>>(out);
}